// round 1
// baseline (speedup 1.0000x reference)
#include <cuda_runtime.h>

// BurstSnn: burst encoder + 2-layer LIF SNN, 32 timesteps.
//   x  [B,187] f32, W1 [50,187] f32, W2 [5,50] f32
//   out: spk_rec [32,B,5] f32  followed by  counts [B] f32
//
// One warp per sample. Encoder state (r, th) lives in registers, 6 dims/lane.
// Layer-1 exploits spike sparsity: ballot -> ffs loop over spiking dims,
// each event adds one W1 column (2 hidden units per lane, float2 from smem).
// Layer-2 (50->5) via per-lane partials + butterfly reduce; mem2 replicated.

#define T_STEPS 32
#define DDIM    187
#define HDIM    50
#define CDIM    5
#define W1_STRIDE 52   // padded row stride (even -> float2 aligned)

__global__ __launch_bounds__(256, 4)
void burst_snn_kernel(const float* __restrict__ x,
                      const float* __restrict__ W1,
                      const float* __restrict__ W2,
                      float* __restrict__ out,
                      int B)
{
    __shared__ __align__(16) float sW1[DDIM * W1_STRIDE];  // [d][h], transposed

    const int tid = threadIdx.x;
    // Load W1 transposed into shared: sW1[d*52 + h] = W1[h*187 + d]
    for (int i = tid; i < DDIM * HDIM; i += blockDim.x) {
        int h = i / DDIM;
        int d = i - h * DDIM;
        sW1[d * W1_STRIDE + h] = W1[i];
    }
    __syncthreads();

    const int lane = tid & 31;
    const int warp = tid >> 5;
    const int b = blockIdx.x * (blockDim.x >> 5) + warp;
    if (b >= B) return;

    const float INIT_TH = 0.125f;
    const float BETA = 0.9f;

    // ---- encoder state: dims d = lane + 32*j, j = 0..5 ----
    float r[6], th[6];
#pragma unroll
    for (int j = 0; j < 6; j++) {
        int d = lane + 32 * j;
        r[j]  = (d < DDIM) ? x[(size_t)b * DDIM + d] : -1.0f;  // -1 never spikes
        th[j] = INIT_TH;
    }

    // ---- W2 rows in registers: lane l owns hidden units 2l, 2l+1 (l<25) ----
    const bool act = (lane < 25);
    float w2a[CDIM], w2b[CDIM];
#pragma unroll
    for (int c = 0; c < CDIM; c++) {
        w2a[c] = act ? W2[c * HDIM + 2 * lane]     : 0.0f;
        w2b[c] = act ? W2[c * HDIM + 2 * lane + 1] : 0.0f;
    }

    float m1a = 0.0f, m1b = 0.0f;
    float m2[CDIM];
#pragma unroll
    for (int c = 0; c < CDIM; c++) m2[c] = 0.0f;
    float cnt = 0.0f;

    const float* wbase = sW1 + 2 * lane;   // this lane's column pair base

    float* spk_out = out + (size_t)b * CDIM;
    const size_t t_stride = (size_t)B * CDIM;

    for (int t = 0; t < T_STEPS; t++) {
        // ---------- burst encoder ----------
        unsigned masks[6];
#pragma unroll
        for (int j = 0; j < 6; j++) {
            bool s = (r[j] >= th[j]);
            masks[j] = __ballot_sync(0xffffffffu, s);
            if (s) { r[j] -= th[j]; th[j] *= 2.0f; cnt += 1.0f; }
            else   { th[j] = INIT_TH; }
        }

        // ---------- layer 1: leak + sparse column accumulation ----------
        m1a *= BETA; m1b *= BETA;
#pragma unroll
        for (int j = 0; j < 6; j++) {
            unsigned m = masks[j];
            while (m) {                       // warp-uniform loop (ballot result)
                int src = __ffs(m) - 1;
                m &= (m - 1);
                int d = src + 32 * j;
                float2 w = make_float2(0.0f, 0.0f);
                if (act) w = *(const float2*)(wbase + d * W1_STRIDE);
                m1a += w.x;
                m1b += w.y;
            }
        }
        bool s1a = (m1a > 1.0f); if (s1a) m1a -= 1.0f;
        bool s1b = (m1b > 1.0f); if (s1b) m1b -= 1.0f;

        // ---------- layer 2: partials + butterfly reduce ----------
        float p[CDIM];
#pragma unroll
        for (int c = 0; c < CDIM; c++) {
            float v = s1a ? w2a[c] : 0.0f;
            if (s1b) v += w2b[c];
            p[c] = v;
        }
#pragma unroll
        for (int off = 16; off > 0; off >>= 1) {
#pragma unroll
            for (int c = 0; c < CDIM; c++)
                p[c] += __shfl_xor_sync(0xffffffffu, p[c], off);
        }

        float spk2v = 0.0f;
#pragma unroll
        for (int c = 0; c < CDIM; c++) {
            m2[c] = BETA * m2[c] + p[c];
            float s2 = (m2[c] > 1.0f) ? 1.0f : 0.0f;
            m2[c] -= s2;
            if (lane == c) spk2v = s2;
        }
        if (lane < CDIM)
            spk_out[(size_t)t * t_stride + lane] = spk2v;
    }

    // ---------- spike counts ----------
#pragma unroll
    for (int off = 16; off > 0; off >>= 1)
        cnt += __shfl_xor_sync(0xffffffffu, cnt, off);
    if (lane == 0)
        out[(size_t)T_STEPS * t_stride + b] = cnt;
}

extern "C" void kernel_launch(void* const* d_in, const int* in_sizes, int n_in,
                              void* d_out, int out_size)
{
    const float* x  = (const float*)d_in[0];
    const float* W1 = (const float*)d_in[1];
    const float* W2 = (const float*)d_in[2];
    float* out = (float*)d_out;

    int B = in_sizes[0] / DDIM;
    int warps_per_block = 256 / 32;
    int blocks = (B + warps_per_block - 1) / warps_per_block;
    burst_snn_kernel<<<blocks, 256>>>(x, W1, W2, out, B);
}

// round 2
// speedup vs baseline: 1.3648x; 1.3648x over previous
#include <cuda_runtime.h>

// BurstSnn: burst encoder + 2-layer LIF SNN, 32 timesteps.
//   x [B,187] f32, W1 [50,187] f32, W2 [5,50] f32
//   out: spk_rec [32,B,5] f32 then counts [B] f32
//
// TWO samples per warp (16 lanes each). Per half-warp:
//   - encoder: 12 groups of 16 dims, ballot -> 16-bit mask
//   - layer 1 sparse: divergent-lockstep event loops (cost ~ max of halves),
//     4 hidden units per lane, packed f32x2 accumulation
//   - dead-group skipping: 2 consecutive empty ballots => group silent forever
//   - layer 2: 4-level butterfly within the 16-lane half

#define T_STEPS 32
#define DDIM 187
#define HDIM 50
#define CDIM 5
#define NGRP 12            // ceil(187/16)

__device__ __forceinline__ void addx2(unsigned long long &a, unsigned long long b) {
    asm("add.rn.f32x2 %0, %1, %2;" : "=l"(a) : "l"(a), "l"(b));
}
__device__ __forceinline__ void mulx2(unsigned long long &a, unsigned long long b) {
    asm("mul.rn.f32x2 %0, %1, %2;" : "=l"(a) : "l"(a), "l"(b));
}
__device__ __forceinline__ unsigned long long packx2(float lo, float hi) {
    unsigned long long r; asm("mov.b64 %0, {%1,%2};" : "=l"(r) : "f"(lo), "f"(hi)); return r;
}
__device__ __forceinline__ void unpackx2(unsigned long long v, float &lo, float &hi) {
    asm("mov.b64 {%0,%1}, %2;" : "=f"(lo), "=f"(hi) : "l"(v));
}

__global__ __launch_bounds__(256, 3)
void burst_snn_kernel(const float* __restrict__ x,
                      const float* __restrict__ W1,
                      const float* __restrict__ W2,
                      float* __restrict__ out, int B)
{
    // sW1[d][u]: W1 transposed, 64-wide padded rows (units >=50 zeroed)
    __shared__ __align__(16) float sW1[DDIM * 64];

    const int tid = threadIdx.x;
    for (int i = tid; i < DDIM * 64; i += 256) {
        int d = i >> 6, u = i & 63;
        sW1[i] = (u < HDIM) ? W1[u * DDIM + d] : 0.0f;
    }
    __syncthreads();

    const int lane  = tid & 31;
    const int hl    = lane & 15;          // lane within half
    const int half  = lane >> 4;
    const int warpg = blockIdx.x * 8 + (tid >> 5);
    const int b     = warpg * 2 + half;   // consecutive samples per warp
    const bool valid = (b < B);

    const float INIT_TH = 0.125f;
    const unsigned long long BETA2 = packx2(0.9f, 0.9f);

    // encoder state: dim d = hl + 16*j
    float r[NGRP], th[NGRP];
    const float* xb = x + (size_t)b * DDIM;
#pragma unroll
    for (int j = 0; j < NGRP; j++) {
        int d = hl + 16 * j;
        r[j]  = (valid && d < DDIM) ? xb[d] : -1.0f;   // -1 never spikes
        th[j] = INIT_TH;
    }

    // W2 rows for this lane's 4 hidden units (4hl .. 4hl+3)
    float w2r[4][CDIM];
#pragma unroll
    for (int u = 0; u < 4; u++) {
        int hu = 4 * hl + u;
#pragma unroll
        for (int c = 0; c < CDIM; c++)
            w2r[u][c] = (hu < HDIM) ? W2[c * HDIM + hu] : 0.0f;
    }

    unsigned long long m01 = 0ull, m23 = 0ull;   // packed mem1 for 4 units
    float m2[CDIM] = {0, 0, 0, 0, 0};
    int cnt = 0;
    unsigned alive = 0xfffu, prevz = 0u;

    const char* wb = (const char*)sW1 + hl * 16;  // this lane's 4-unit slot
    const int shamt = lane & 16;                  // half-select shift for ballot
    float* po = out + (size_t)b * CDIM + hl;
    const size_t tstride = (size_t)B * CDIM;

#pragma unroll 1
    for (int t = 0; t < T_STEPS; t++) {
        // LIF1 leak (packed)
        mulx2(m01, BETA2); mulx2(m23, BETA2);

        // -------- burst encoder + sparse layer-1 accumulation --------
#pragma unroll
        for (int j = 0; j < NGRP; j++) {
            if (!(alive & (1u << j))) continue;         // group dead forever
            bool s = (r[j] >= th[j]);
            unsigned bal = __ballot_sync(0xffffffffu, s);
            cnt += s;
            if (s) { r[j] -= th[j]; th[j] *= 2.0f; }
            else   { th[j] = INIT_TH; }
            if (bal == 0u) {
                // after an empty step, all th are back at 0.125 next step;
                // two consecutive empty ballots => r < 0.125 forever => dead
                if (prevz & (1u << j)) alive &= ~(1u << j);
                prevz |= (1u << j);
                continue;
            }
            prevz &= ~(1u << j);
            unsigned mh = (bal >> shamt) & 0xffffu;     // this half's events
            while (mh) {                                 // lockstep across halves
                int src = __ffs(mh) - 1;
                mh &= mh - 1;
                const ulonglong2 w = *(const ulonglong2*)(wb + j * 4096 + src * 256);
                addx2(m01, w.x);
                addx2(m23, w.y);
            }
        }

        // -------- LIF1 threshold / reset --------
        float a0, a1, a2, a3;
        unpackx2(m01, a0, a1); unpackx2(m23, a2, a3);
        bool s0 = a0 > 1.0f, s1 = a1 > 1.0f, s2 = a2 > 1.0f, s3 = a3 > 1.0f;
        if (s0) a0 -= 1.0f; if (s1) a1 -= 1.0f;
        if (s2) a2 -= 1.0f; if (s3) a3 -= 1.0f;
        m01 = packx2(a0, a1); m23 = packx2(a2, a3);

        // -------- layer 2: partials + 4-level half-warp butterfly --------
        float p[CDIM];
#pragma unroll
        for (int c = 0; c < CDIM; c++) {
            float v = s0 ? w2r[0][c] : 0.0f;
            if (s1) v += w2r[1][c];
            if (s2) v += w2r[2][c];
            if (s3) v += w2r[3][c];
            p[c] = v;
        }
#pragma unroll
        for (int off = 8; off; off >>= 1)
#pragma unroll
            for (int c = 0; c < CDIM; c++)
                p[c] += __shfl_xor_sync(0xffffffffu, p[c], off);

        // -------- LIF2 + output --------
        float sv = 0.0f;
#pragma unroll
        for (int c = 0; c < CDIM; c++) {
            m2[c] = 0.9f * m2[c] + p[c];
            float sp = (m2[c] > 1.0f) ? 1.0f : 0.0f;
            m2[c] -= sp;
            if (hl == c) sv = sp;
        }
        if (valid && hl < CDIM) po[(size_t)t * tstride] = sv;
    }

    // -------- spike counts (exact integer) --------
#pragma unroll
    for (int off = 8; off; off >>= 1)
        cnt += __shfl_xor_sync(0xffffffffu, cnt, off);
    if (valid && hl == 0)
        out[(size_t)T_STEPS * tstride + b] = (float)cnt;
}

extern "C" void kernel_launch(void* const* d_in, const int* in_sizes, int n_in,
                              void* d_out, int out_size)
{
    const float* x  = (const float*)d_in[0];
    const float* W1 = (const float*)d_in[1];
    const float* W2 = (const float*)d_in[2];
    float* out = (float*)d_out;

    int B = in_sizes[0] / DDIM;
    int blocks = (B + 15) / 16;   // 8 warps/block, 2 samples/warp
    burst_snn_kernel<<<blocks, 256>>>(x, W1, W2, out, B);
}

// round 3
// speedup vs baseline: 1.6905x; 1.2386x over previous
#include <cuda_runtime.h>

// BurstSnn: burst encoder + 2-layer LIF SNN, 32 timesteps.
// x [B,187] f32, W1 [50,187] f32, W2 [5,50] f32
// out: spk_rec [32,B,5] f32 then counts [B] f32
//
// Two samples/warp (16-lane halves). Sparse event processing for BOTH layers.
// Key: burst coding self-extinguishes; once alive==0 and no L1/L2 spikes in a
// step, all future outputs are exactly 0 -> break + zero-fill.

#define T_STEPS 32
#define DDIM 187
#define HDIM 50
#define CDIM 5
#define NGRP 12
#define W2S  52

__device__ __forceinline__ void addx2(unsigned long long &a, unsigned long long b) {
    asm("add.rn.f32x2 %0, %1, %2;" : "=l"(a) : "l"(a), "l"(b));
}
__device__ __forceinline__ void mulx2(unsigned long long &a, unsigned long long b) {
    asm("mul.rn.f32x2 %0, %1, %2;" : "=l"(a) : "l"(a), "l"(b));
}
__device__ __forceinline__ unsigned long long packx2(float lo, float hi) {
    unsigned long long r; asm("mov.b64 %0, {%1,%2};" : "=l"(r) : "f"(lo), "f"(hi)); return r;
}
__device__ __forceinline__ void unpackx2(unsigned long long v, float &lo, float &hi) {
    asm("mov.b64 {%0,%1}, %2;" : "=f"(lo), "=f"(hi) : "l"(v));
}

__global__ __launch_bounds__(256, 4)
void burst_snn_kernel(const float* __restrict__ x,
                      const float* __restrict__ W1,
                      const float* __restrict__ W2,
                      float* __restrict__ out, int B)
{
    // W1 transposed: sW1[d*64 + u] (u >= 50 zero). 256B per d-row -> LDS.128/lane.
    __shared__ __align__(16) float sW1[DDIM * 64];
    __shared__ float sW2[CDIM * W2S];

    const int tid = threadIdx.x;
    for (int i = tid; i < DDIM * 64; i += 256) {
        int d = i >> 6, u = i & 63;
        sW1[i] = (u < HDIM) ? W1[u * DDIM + d] : 0.0f;
    }
    for (int i = tid; i < CDIM * W2S; i += 256) {
        int c = i / W2S, h = i - c * W2S;
        sW2[i] = (h < HDIM) ? W2[c * HDIM + h] : 0.0f;
    }
    __syncthreads();

    const int lane  = tid & 31;
    const int hl    = lane & 15;
    const int half  = lane >> 4;
    const int b     = (blockIdx.x * 8 + (tid >> 5)) * 2 + half;
    const bool valid = (b < B);

    const float INIT_TH = 0.125f;
    const unsigned long long BETA2 = packx2(0.9f, 0.9f);

    // encoder state: dim d = hl + 16*j
    float r[NGRP], th[NGRP];
    const float* xb = x + (size_t)b * DDIM;
#pragma unroll
    for (int j = 0; j < NGRP; j++) {
        int d = hl + 16 * j;
        r[j]  = (valid && d < DDIM) ? xb[d] : -1.0f;
        th[j] = INIT_TH;
    }

    unsigned long long m01 = 0ull, m23 = 0ull;  // mem1 for units 4hl..4hl+3
    float m2 = 0.0f;                            // class = hl (lanes hl<5)
    int cnt = 0;
    unsigned alive = 0xfffu, prevz = 0u;

    const char*  wb  = (const char*)sW1 + hl * 16;
    const float* w2b = sW2 + hl * W2S;          // class row (lanes hl<5)
    const int shamt = lane & 16;
    float* po = out + (size_t)b * CDIM + hl;
    const size_t tstride = (size_t)B * CDIM;

    int t = 0;
#pragma unroll 1
    for (; t < T_STEPS; t++) {
        mulx2(m01, BETA2); mulx2(m23, BETA2);

        // -------- encoder + sparse layer-1 --------
#pragma unroll
        for (int j = 0; j < NGRP; j++) {
            if (!(alive & (1u << j))) continue;
            bool s = (r[j] >= th[j]);
            unsigned bal = __ballot_sync(0xffffffffu, s);
            cnt += s;
            if (s) { r[j] -= th[j]; th[j] *= 2.0f; }
            else   { th[j] = INIT_TH; }
            if (bal == 0u) {
                if (prevz & (1u << j)) alive &= ~(1u << j);  // dead forever
                prevz |= (1u << j);
                continue;
            }
            prevz &= ~(1u << j);
            unsigned mh = (bal >> shamt) & 0xffffu;
            while (mh) {                         // lockstep across halves
                int i0 = __ffs(mh) - 1; mh &= mh - 1;
                const ulonglong2 w0 = *(const ulonglong2*)(wb + j * 4096 + i0 * 256);
                if (mh) {
                    int i1 = __ffs(mh) - 1; mh &= mh - 1;
                    const ulonglong2 w1 = *(const ulonglong2*)(wb + j * 4096 + i1 * 256);
                    addx2(m01, w0.x); addx2(m23, w0.y);
                    addx2(m01, w1.x); addx2(m23, w1.y);
                } else {
                    addx2(m01, w0.x); addx2(m23, w0.y);
                }
            }
        }

        // -------- LIF1 threshold / reset --------
        float a0, a1, a2, a3;
        unpackx2(m01, a0, a1); unpackx2(m23, a2, a3);
        bool s0 = a0 > 1.0f, s1 = a1 > 1.0f, s2 = a2 > 1.0f, s3 = a3 > 1.0f;
        if (s0) a0 -= 1.0f; if (s1) a1 -= 1.0f;
        if (s2) a2 -= 1.0f; if (s3) a3 -= 1.0f;
        m01 = packx2(a0, a1); m23 = packx2(a2, a3);

        // -------- layer 2: ballot-collected sparse gather --------
        unsigned b0 = __ballot_sync(0xffffffffu, s0);
        unsigned b1 = __ballot_sync(0xffffffffu, s1);
        unsigned b2m = __ballot_sync(0xffffffffu, s2);
        unsigned b3 = __ballot_sync(0xffffffffu, s3);
        unsigned anyS1 = b0 | b1 | b2m | b3;

        float cur2 = 0.0f;
        if (anyS1) {
            unsigned f;
            f = (b0 >> shamt) & 0xffffu;
            while (f) { int i = __ffs(f) - 1; f &= f - 1;
                        if (hl < CDIM) cur2 += w2b[4 * i + 0]; }
            f = (b1 >> shamt) & 0xffffu;
            while (f) { int i = __ffs(f) - 1; f &= f - 1;
                        if (hl < CDIM) cur2 += w2b[4 * i + 1]; }
            f = (b2m >> shamt) & 0xffffu;
            while (f) { int i = __ffs(f) - 1; f &= f - 1;
                        if (hl < CDIM) cur2 += w2b[4 * i + 2]; }
            f = (b3 >> shamt) & 0xffffu;
            while (f) { int i = __ffs(f) - 1; f &= f - 1;
                        if (hl < CDIM) cur2 += w2b[4 * i + 3]; }
        }

        // -------- LIF2 + output --------
        m2 = 0.9f * m2 + cur2;
        bool sp2 = (hl < CDIM) && (m2 > 1.0f);
        if (sp2) m2 -= 1.0f;
        if (valid && hl < CDIM) po[(size_t)t * tstride] = sp2 ? 1.0f : 0.0f;

        // -------- quiescence: everything zero from here on --------
        unsigned anyS2 = __ballot_sync(0xffffffffu, sp2);
        if (alive == 0u && anyS1 == 0u && anyS2 == 0u) { t++; break; }
    }

    // zero-fill remaining steps
    if (valid && hl < CDIM)
        for (; t < T_STEPS; t++) po[(size_t)t * tstride] = 0.0f;

    // -------- spike counts --------
#pragma unroll
    for (int off = 8; off; off >>= 1)
        cnt += __shfl_xor_sync(0xffffffffu, cnt, off);
    if (valid && hl == 0)
        out[(size_t)T_STEPS * tstride + b] = (float)cnt;
}

extern "C" void kernel_launch(void* const* d_in, const int* in_sizes, int n_in,
                              void* d_out, int out_size)
{
    const float* x  = (const float*)d_in[0];
    const float* W1 = (const float*)d_in[1];
    const float* W2 = (const float*)d_in[2];
    float* out = (float*)d_out;

    int B = in_sizes[0] / DDIM;
    int blocks = (B + 15) / 16;   // 8 warps/block, 2 samples/warp
    burst_snn_kernel<<<blocks, 256>>>(x, W1, W2, out, B);
}